// round 6
// baseline (speedup 1.0000x reference)
#include <cuda_runtime.h>
#include <cuda_bf16.h>
#include <math.h>
#include <stdint.h>

#define Bb    4
#define DIMC  192
#define Hh    256
#define Wc    256
#define NHEAD 6
#define KBPE  32
#define NWIN  4096
#define TTOT  (Bb*Hh*Wc)   // 262144 tokens

typedef unsigned long long ull;
typedef __nv_bfloat16 bf16;

// ---------------- scratch ----------------
__device__ __align__(16) float g_xres[(size_t)TTOT*DIMC];   // shortcut; later fc2 fp32 out
__device__ __align__(16) bf16  g_xnh [(size_t)TTOT*DIMC];
__device__ __align__(16) bf16  g_xnl [(size_t)TTOT*DIMC];
__device__ __align__(16) bf16  g_bwh [(size_t)TTOT*KBPE];
__device__ __align__(16) bf16  g_bwl [(size_t)TTOT*KBPE];
__device__ __align__(16) float g_qkv [(size_t)TTOT*3*DIMC]; // aliased: bf16 hi|lo planes
__device__ __align__(16) float g_bqk [(size_t)TTOT*2*DIMC]; // aliased: bf16 hi|lo planes
__device__ __align__(16) bf16  g_ath [(size_t)TTOT*DIMC];
__device__ __align__(16) bf16  g_atl [(size_t)TTOT*DIMC];
__device__ __align__(16) float g_xh2 [(size_t)TTOT*DIMC];
__device__ __align__(16) bf16  g_h1h [(size_t)TTOT*4*DIMC];
__device__ __align__(16) bf16  g_h1l [(size_t)TTOT*4*DIMC];
// weights transposed [N,K], split hi/lo
__device__ __align__(16) bf16 g_wqh[576*192], g_wql[576*192];
__device__ __align__(16) bf16 g_wbh[384*32],  g_wbl[384*32];
__device__ __align__(16) bf16 g_wph[192*192], g_wpl[192*192];
__device__ __align__(16) bf16 g_w1h[768*192], g_w1l[768*192];
__device__ __align__(16) bf16 g_w2h[192*768], g_w2l[192*768];

// ---------------- helpers ----------------
__device__ __forceinline__ float gelu_exact(float x) {
    return 0.5f * x * (1.0f + erff(x * 0.70710678118654752440f));
}
__device__ __forceinline__ uint32_t smem_u32(const void* p) {
    uint32_t a;
    asm("{ .reg .u64 t; cvta.to.shared.u64 t, %1; cvt.u32.u64 %0, t; }" : "=r"(a) : "l"(p));
    return a;
}
__device__ __forceinline__ void split_store(bf16* hi, bf16* lo, size_t idx, float v) {
    bf16 h = __float2bfloat16(v);
    hi[idx] = h;
    lo[idx] = __float2bfloat16(v - __bfloat162float(h));
}
__device__ __forceinline__ float ex2f(float x) {
    float r; asm("ex2.approx.f32 %0, %1;" : "=f"(r) : "f"(x)); return r;
}
// pack two f32 -> bf16x2 (lo = a, hi = b)
__device__ __forceinline__ uint32_t packbf(float a, float b) {
    uint32_t r; asm("cvt.rn.bf16x2.f32 %0, %1, %2;" : "=r"(r) : "f"(b), "f"(a)); return r;
}
__device__ __forceinline__ float bfround(float x) {
    return __bfloat162float(__float2bfloat16(x));
}

// cp.async
__device__ __forceinline__ void cpa16(uint32_t dst, const void* src) {
    asm volatile("cp.async.ca.shared.global [%0], [%1], 16;" :: "r"(dst), "l"(src));
}
#define CP_COMMIT() asm volatile("cp.async.commit_group;" ::: "memory")
#define CP_WAIT1()  asm volatile("cp.async.wait_group 1;" ::: "memory")
#define CP_WAIT0()  asm volatile("cp.async.wait_group 0;" ::: "memory")

// ldmatrix (non-trans) x4
__device__ __forceinline__ void ldsm_x4(uint32_t* r, uint32_t addr) {
    asm volatile("ldmatrix.sync.aligned.m8n8.x4.shared.b16 {%0,%1,%2,%3}, [%4];"
        : "=r"(r[0]), "=r"(r[1]), "=r"(r[2]), "=r"(r[3]) : "r"(addr));
}
// bf16 mma m16n8k16, fp32 acc
__device__ __forceinline__ void mma_bf16(float* d, const uint32_t* a, const uint32_t* b) {
    asm volatile("mma.sync.aligned.m16n8k16.row.col.f32.bf16.bf16.f32 "
        "{%0,%1,%2,%3}, {%4,%5,%6,%7}, {%8,%9}, {%0,%1,%2,%3};"
        : "+f"(d[0]), "+f"(d[1]), "+f"(d[2]), "+f"(d[3])
        : "r"(a[0]), "r"(a[1]), "r"(a[2]), "r"(a[3]), "r"(b[0]), "r"(b[1]));
}

// =====================================================================
// k_wt: weight [K,N] fp32 -> [N,K] bf16 hi/lo
// =====================================================================
__global__ __launch_bounds__(256) void k_wt(const float* __restrict__ w,
                                            bf16* __restrict__ hi, bf16* __restrict__ lo,
                                            int K, int N)
{
    __shared__ float sm[32][33];
    int n0 = blockIdx.x * 32, k0 = blockIdx.y * 32;
    int tx = threadIdx.x, ty = threadIdx.y;
    #pragma unroll
    for (int j = 0; j < 32; j += 8)
        sm[ty + j][tx] = w[(size_t)(k0 + ty + j) * N + n0 + tx];
    __syncthreads();
    #pragma unroll
    for (int j = 0; j < 32; j += 8) {
        int n = n0 + ty + j, k = k0 + tx;
        split_store(hi, lo, (size_t)n * K + k, sm[tx][ty + j]);
    }
}

// =====================================================================
// k_pre: NCHW -> window layout, LN1 -> hi/lo planes, bpe -> hi/lo
// =====================================================================
__global__ __launch_bounds__(256) void k_pre(
    const float* __restrict__ x, const float* __restrict__ bpe,
    const float* __restrict__ w1, const float* __restrict__ b1)
{
    __shared__ float xs[DIMC][33];
    __shared__ float bs[KBPE][33];
    __shared__ float smean[32], srstd[32];
    int w0 = blockIdx.x * 32, h = blockIdx.y, b = blockIdx.z;
    int tid = threadIdx.x, lane = tid & 31, wrp = tid >> 5;

    #pragma unroll
    for (int it = 0; it < 24; it++) {
        int c = it * 8 + wrp;
        xs[c][lane] = x[((size_t)(b*DIMC + c)*Hh + h)*Wc + w0 + lane];
    }
    #pragma unroll
    for (int it = 0; it < 4; it++) {
        int c = it * 8 + wrp;
        bs[c][lane] = bpe[((size_t)(b*KBPE + c)*Hh + h)*Wc + w0 + lane];
    }
    __syncthreads();

    int tok = tid >> 3, g = tid & 7;
    float s = 0.f, sq = 0.f;
    for (int c = g; c < DIMC; c += 8) { float v = xs[c][tok]; s += v; sq += v*v; }
    s  += __shfl_down_sync(0xffffffffu, s, 4, 8);  sq += __shfl_down_sync(0xffffffffu, sq, 4, 8);
    s  += __shfl_down_sync(0xffffffffu, s, 2, 8);  sq += __shfl_down_sync(0xffffffffu, sq, 2, 8);
    s  += __shfl_down_sync(0xffffffffu, s, 1, 8);  sq += __shfl_down_sync(0xffffffffu, sq, 1, 8);
    if (g == 0) {
        float m = s * (1.0f/DIMC);
        float var = sq * (1.0f/DIMC) - m*m;
        smean[tok] = m;
        srstd[tok] = rsqrtf(var + 1e-5f);
    }
    __syncthreads();

    int whh = h >> 3, r = h & 7;
    #pragma unroll
    for (int it = 0; it < 24; it++) {
        int flat = it * 256 + tid;
        int tokj = flat / 192, c = flat - tokj * 192;
        int w = w0 + tokj, ww = w >> 3, cp = w & 7;
        int trow = ((b*32 + whh)*32 + ww)*64 + r*8 + cp;
        float v = xs[c][tokj];
        g_xres[(size_t)trow*DIMC + c] = v;
        float vn = (v - smean[tokj]) * srstd[tokj] * w1[c] + b1[c];
        split_store(g_xnh, g_xnl, (size_t)trow*DIMC + c, vn);
    }
    #pragma unroll
    for (int it = 0; it < 4; it++) {
        int flat = it * 256 + tid;
        int tokj = flat >> 5, c = flat & 31;
        int w = w0 + tokj, ww = w >> 3, cp = w & 7;
        int trow = ((b*32 + whh)*32 + ww)*64 + r*8 + cp;
        split_store(g_bwh, g_bwl, (size_t)trow*KBPE + c, bs[c][tokj]);
    }
}

// =====================================================================
// k_hmma: C = A @ W^T via mma.sync bf16 3-pass split.
// CTA 128x96, KC=16, 8 warps (4x2), warp 32x48 = 2x6 m16n8k16 tiles.
// MODE 0: +bias fp32 ; 1: +bias+res fp32 ; 2: gelu -> bf16 hi/lo ;
// MODE 3: +bias -> bf16 hi/lo (no activation)
// =====================================================================
#define STAGE_B 21504
#define SMEM_HM (2*STAGE_B)

template<int MODE>
__global__ __launch_bounds__(256, 2) void k_hmma(
    const bf16* __restrict__ Ahi, const bf16* __restrict__ Alo,
    const bf16* __restrict__ Bhi, const bf16* __restrict__ Blo,
    const float* __restrict__ bias, const float* __restrict__ res,
    float* __restrict__ Cf, bf16* __restrict__ Chi, bf16* __restrict__ Clo,
    int N, int K)
{
    extern __shared__ char smc[];
    const uint32_t sb = smem_u32(smc);
    const int tid = threadIdx.x, lane = tid & 31, wid = tid >> 5;
    const int bx = blockIdx.x, by = blockIdx.y;
    const int mrow = (wid & 3) * 32, ncol = (wid >> 2) * 48;

    float acc[2][6][4];
    #pragma unroll
    for (int i = 0; i < 2; i++)
        #pragma unroll
        for (int j = 0; j < 6; j++)
            #pragma unroll
            for (int q = 0; q < 4; q++) acc[i][j][q] = 0.f;

    const int a_row_l = ((lane >> 3) & 1) * 8 + (lane & 7);
    const int a_k_l   = (lane >> 4) * 8;
    const int b_n_l   = (lane >> 4) * 8 + (lane & 7);
    const int b_k_l   = ((lane >> 3) & 1) * 8;

    const int nt = K / 16;

    auto load_stage = [&](int s, int k0) {
        uint32_t base = sb + s * STAGE_B;
        #pragma unroll
        for (int it = 0; it < 2; it++) {
            int id = it * 256 + tid;
            int pl = id >> 8, rem = id & 255;
            int row = rem >> 1, seg = rem & 1;
            const bf16* src = (pl ? Alo : Ahi) + (size_t)(by*128 + row) * K + k0 + seg*8;
            cpa16(base + pl*6144 + row*48 + seg*16, src);
        }
        {
            int id = tid;
            int pl = (id >= 192), rem = id - pl*192;
            int row = rem >> 1, seg = rem & 1;
            const bf16* src = (pl ? Blo : Bhi) + (size_t)(bx*96 + row) * K + k0 + seg*8;
            cpa16(base + 12288 + pl*4608 + row*48 + seg*16, src);
        }
        if (tid < 128) {
            int id = 256 + tid;
            int pl = (id >= 192), rem = id - pl*192;
            int row = rem >> 1, seg = rem & 1;
            const bf16* src = (pl ? Blo : Bhi) + (size_t)(bx*96 + row) * K + k0 + seg*8;
            cpa16(base + 12288 + pl*4608 + row*48 + seg*16, src);
        }
        CP_COMMIT();
    };

    load_stage(0, 0);

    for (int t = 0; t < nt; t++) {
        if (t + 1 < nt) { load_stage((t + 1) & 1, (t + 1) * 16); CP_WAIT1(); }
        else            { CP_WAIT0(); }
        __syncthreads();

        uint32_t base = sb + (t & 1) * STAGE_B;
        uint32_t Ah[2][4], Al_[2][4], Bf[6][2];
        #pragma unroll
        for (int mt = 0; mt < 2; mt++) {
            uint32_t off = (mrow + mt*16 + a_row_l) * 48 + a_k_l * 2;
            ldsm_x4(Ah[mt],  base + off);
            ldsm_x4(Al_[mt], base + 6144 + off);
        }
        #pragma unroll
        for (int nb = 0; nb < 3; nb++) {
            uint32_t r4[4];
            ldsm_x4(r4, base + 12288 + (ncol + nb*16 + b_n_l) * 48 + b_k_l * 2);
            Bf[nb*2][0] = r4[0]; Bf[nb*2][1] = r4[1];
            Bf[nb*2+1][0] = r4[2]; Bf[nb*2+1][1] = r4[3];
        }
        #pragma unroll
        for (int mt = 0; mt < 2; mt++)
            #pragma unroll
            for (int nn = 0; nn < 6; nn++) {
                mma_bf16(acc[mt][nn], Ah[mt],  Bf[nn]);
                mma_bf16(acc[mt][nn], Al_[mt], Bf[nn]);
            }
        #pragma unroll
        for (int nb = 0; nb < 3; nb++) {
            uint32_t r4[4];
            ldsm_x4(r4, base + 16896 + (ncol + nb*16 + b_n_l) * 48 + b_k_l * 2);
            Bf[nb*2][0] = r4[0]; Bf[nb*2][1] = r4[1];
            Bf[nb*2+1][0] = r4[2]; Bf[nb*2+1][1] = r4[3];
        }
        #pragma unroll
        for (int mt = 0; mt < 2; mt++)
            #pragma unroll
            for (int nn = 0; nn < 6; nn++)
                mma_bf16(acc[mt][nn], Ah[mt], Bf[nn]);
        __syncthreads();
    }

    // ---- epilogue ----
    const int trow = lane >> 2, tcol = (lane & 3) * 2;
    #pragma unroll
    for (int mt = 0; mt < 2; mt++) {
        #pragma unroll
        for (int nn = 0; nn < 6; nn++) {
            int row0 = by*128 + mrow + mt*16 + trow;
            int col  = bx*96 + ncol + nn*8 + tcol;
            float b0 = bias[col], b1 = bias[col + 1];
            #pragma unroll
            for (int hh = 0; hh < 2; hh++) {
                int row = row0 + hh * 8;
                float v0 = acc[mt][nn][hh*2]   + b0;
                float v1 = acc[mt][nn][hh*2+1] + b1;
                size_t idx = (size_t)row * N + col;
                if (MODE == 1) { v0 += res[idx]; v1 += res[idx + 1]; }
                if (MODE == 2) {
                    split_store(Chi, Clo, idx,     gelu_exact(v0));
                    split_store(Chi, Clo, idx + 1, gelu_exact(v1));
                } else if (MODE == 3) {
                    split_store(Chi, Clo, idx,     v0);
                    split_store(Chi, Clo, idx + 1, v1);
                } else {
                    *(float2*)(Cf + idx) = make_float2(v0, v1);
                }
            }
        }
    }
}

// =====================================================================
// k_attn2: HMMA attention. Block = (head, window), 2 warps, 64 threads.
// S = [Q|Bq][64,64] @ [K|Bk][64,64]^T (3-pass hi/lo), softmax in regs,
// P repacked in-register to A-frags, P@V (3-pass). 45KB static smem.
// =====================================================================
#define APITCH 144
#define QH_OFF 0
#define QL_OFF 9216
#define KH_OFF 18432
#define KL_OFF 27648
#define VH_OFF 36864
#define VL_OFF 41472

__global__ __launch_bounds__(64) void k_attn2(
    const bf16* __restrict__ qkvh, const bf16* __restrict__ qkvl,
    const bf16* __restrict__ bqkh, const bf16* __restrict__ bqkl)
{
    __shared__ __align__(16) char sm[46080];
    const uint32_t sb = smem_u32(sm);
    const int hd = blockIdx.x, win = blockIdx.y;
    const int tid = threadIdx.x, lane = tid & 31, wrp = tid >> 5;
    const int t0 = win * 64, qo = hd * 32;

    // ---- load Q|Bq, K|Bk rows (one row per thread), V transposed ----
    {
        int i = tid;
        const uint4* qh = (const uint4*)(qkvh + (size_t)(t0+i)*576 + qo);
        const uint4* ql = (const uint4*)(qkvl + (size_t)(t0+i)*576 + qo);
        const uint4* kh = (const uint4*)(qkvh + (size_t)(t0+i)*576 + 192 + qo);
        const uint4* kl = (const uint4*)(qkvl + (size_t)(t0+i)*576 + 192 + qo);
        const uint4* bh = (const uint4*)(bqkh + (size_t)(t0+i)*384 + qo);
        const uint4* bl = (const uint4*)(bqkl + (size_t)(t0+i)*384 + qo);
        const uint4* ch = (const uint4*)(bqkh + (size_t)(t0+i)*384 + 192 + qo);
        const uint4* cl = (const uint4*)(bqkl + (size_t)(t0+i)*384 + 192 + qo);
        uint4* dqh = (uint4*)(sm + QH_OFF + i*APITCH);
        uint4* dql = (uint4*)(sm + QL_OFF + i*APITCH);
        uint4* dkh = (uint4*)(sm + KH_OFF + i*APITCH);
        uint4* dkl = (uint4*)(sm + KL_OFF + i*APITCH);
        #pragma unroll
        for (int j = 0; j < 4; j++) {
            dqh[j] = qh[j]; dqh[4+j] = bh[j];
            dql[j] = ql[j]; dql[4+j] = bl[j];
            dkh[j] = kh[j]; dkh[4+j] = ch[j];
            dkl[j] = kl[j]; dkl[4+j] = cl[j];
        }
    }
    #pragma unroll
    for (int it = 0; it < 32; it++) {
        int t = it*2 + wrp;
        int d = lane;
        *(bf16*)(sm + VH_OFF + d*APITCH + t*2) = qkvh[(size_t)(t0+t)*576 + 384 + qo + d];
        *(bf16*)(sm + VL_OFF + d*APITCH + t*2) = qkvl[(size_t)(t0+t)*576 + 384 + qo + d];
    }
    __syncthreads();

    const int m0 = wrp * 32;
    const int a_row_l = ((lane >> 3) & 1) * 8 + (lane & 7);
    const int a_k_l   = (lane >> 4) * 8;
    const int b_n_l   = (lane >> 4) * 8 + (lane & 7);
    const int b_k_l   = ((lane >> 3) & 1) * 8;

    // ---- S = Qcat @ Kcat^T, 3-pass ----
    float sacc[2][8][4];
    #pragma unroll
    for (int i = 0; i < 2; i++)
        #pragma unroll
        for (int j = 0; j < 8; j++)
            #pragma unroll
            for (int q = 0; q < 4; q++) sacc[i][j][q] = 0.f;

    #pragma unroll
    for (int kt = 0; kt < 4; kt++) {
        uint32_t Ah[2][4], Al[2][4], Bh[8][2], Bl[8][2];
        #pragma unroll
        for (int mt = 0; mt < 2; mt++) {
            uint32_t off = (m0 + mt*16 + a_row_l) * APITCH + (kt*16 + a_k_l) * 2;
            ldsm_x4(Ah[mt], sb + QH_OFF + off);
            ldsm_x4(Al[mt], sb + QL_OFF + off);
        }
        #pragma unroll
        for (int nb = 0; nb < 4; nb++) {
            uint32_t r4[4];
            uint32_t off = (nb*16 + b_n_l) * APITCH + (kt*16 + b_k_l) * 2;
            ldsm_x4(r4, sb + KH_OFF + off);
            Bh[nb*2][0] = r4[0]; Bh[nb*2][1] = r4[1];
            Bh[nb*2+1][0] = r4[2]; Bh[nb*2+1][1] = r4[3];
            ldsm_x4(r4, sb + KL_OFF + off);
            Bl[nb*2][0] = r4[0]; Bl[nb*2][1] = r4[1];
            Bl[nb*2+1][0] = r4[2]; Bl[nb*2+1][1] = r4[3];
        }
        #pragma unroll
        for (int mt = 0; mt < 2; mt++)
            #pragma unroll
            for (int nn = 0; nn < 8; nn++) {
                mma_bf16(sacc[mt][nn], Ah[mt], Bh[nn]);
                mma_bf16(sacc[mt][nn], Ah[mt], Bl[nn]);
                mma_bf16(sacc[mt][nn], Al[mt], Bh[nn]);
            }
    }

    // ---- softmax over each row of 64 (quad shfl reduce) ----
    const float cs = 0.25503486325804f;   // (1/sqrt(32)) * log2(e)
    float rs[2][2];
    #pragma unroll
    for (int mt = 0; mt < 2; mt++) {
        float mA = -1e30f, mB = -1e30f;
        #pragma unroll
        for (int n = 0; n < 8; n++) {
            mA = fmaxf(mA, fmaxf(sacc[mt][n][0], sacc[mt][n][1]));
            mB = fmaxf(mB, fmaxf(sacc[mt][n][2], sacc[mt][n][3]));
        }
        mA = fmaxf(mA, __shfl_xor_sync(0xffffffffu, mA, 1));
        mA = fmaxf(mA, __shfl_xor_sync(0xffffffffu, mA, 2));
        mB = fmaxf(mB, __shfl_xor_sync(0xffffffffu, mB, 1));
        mB = fmaxf(mB, __shfl_xor_sync(0xffffffffu, mB, 2));
        float sA = 0.f, sB = 0.f;
        #pragma unroll
        for (int n = 0; n < 8; n++) {
            float p0 = ex2f((sacc[mt][n][0] - mA) * cs);
            float p1 = ex2f((sacc[mt][n][1] - mA) * cs);
            float p2 = ex2f((sacc[mt][n][2] - mB) * cs);
            float p3 = ex2f((sacc[mt][n][3] - mB) * cs);
            sacc[mt][n][0] = p0; sacc[mt][n][1] = p1;
            sacc[mt][n][2] = p2; sacc[mt][n][3] = p3;
            sA += p0 + p1; sB += p2 + p3;
        }
        sA += __shfl_xor_sync(0xffffffffu, sA, 1);
        sA += __shfl_xor_sync(0xffffffffu, sA, 2);
        sB += __shfl_xor_sync(0xffffffffu, sB, 1);
        sB += __shfl_xor_sync(0xffffffffu, sB, 2);
        rs[mt][0] = 1.0f / sA;
        rs[mt][1] = 1.0f / sB;
    }

    // ---- out = P @ V, 3-pass (P hi/lo in-register repack) ----
    float oacc[2][4][4];
    #pragma unroll
    for (int i = 0; i < 2; i++)
        #pragma unroll
        for (int j = 0; j < 4; j++)
            #pragma unroll
            for (int q = 0; q < 4; q++) oacc[i][j][q] = 0.f;

    #pragma unroll
    for (int kt = 0; kt < 4; kt++) {
        uint32_t Ph[2][4], Pl[2][4];
        #pragma unroll
        for (int mt = 0; mt < 2; mt++) {
            float p00 = sacc[mt][2*kt][0],   p01 = sacc[mt][2*kt][1];
            float p02 = sacc[mt][2*kt][2],   p03 = sacc[mt][2*kt][3];
            float p10 = sacc[mt][2*kt+1][0], p11 = sacc[mt][2*kt+1][1];
            float p12 = sacc[mt][2*kt+1][2], p13 = sacc[mt][2*kt+1][3];
            Ph[mt][0] = packbf(p00, p01);
            Ph[mt][1] = packbf(p02, p03);
            Ph[mt][2] = packbf(p10, p11);
            Ph[mt][3] = packbf(p12, p13);
            Pl[mt][0] = packbf(p00 - bfround(p00), p01 - bfround(p01));
            Pl[mt][1] = packbf(p02 - bfround(p02), p03 - bfround(p03));
            Pl[mt][2] = packbf(p10 - bfround(p10), p11 - bfround(p11));
            Pl[mt][3] = packbf(p12 - bfround(p12), p13 - bfround(p13));
        }
        uint32_t Vh[4][2], Vl[4][2];
        #pragma unroll
        for (int nb = 0; nb < 2; nb++) {
            uint32_t r4[4];
            uint32_t off = (nb*16 + b_n_l) * APITCH + (kt*16 + b_k_l) * 2;
            ldsm_x4(r4, sb + VH_OFF + off);
            Vh[nb*2][0] = r4[0]; Vh[nb*2][1] = r4[1];
            Vh[nb*2+1][0] = r4[2]; Vh[nb*2+1][1] = r4[3];
            ldsm_x4(r4, sb + VL_OFF + off);
            Vl[nb*2][0] = r4[0]; Vl[nb*2][1] = r4[1];
            Vl[nb*2+1][0] = r4[2]; Vl[nb*2+1][1] = r4[3];
        }
        #pragma unroll
        for (int mt = 0; mt < 2; mt++)
            #pragma unroll
            for (int nn = 0; nn < 4; nn++) {
                mma_bf16(oacc[mt][nn], Ph[mt], Vh[nn]);
                mma_bf16(oacc[mt][nn], Ph[mt], Vl[nn]);
                mma_bf16(oacc[mt][nn], Pl[mt], Vh[nn]);
            }
    }

    // ---- epilogue: scale by 1/rowsum, split-store bf16 hi/lo ----
    const int trow = lane >> 2, tcol = (lane & 3) * 2;
    #pragma unroll
    for (int mt = 0; mt < 2; mt++) {
        #pragma unroll
        for (int nn = 0; nn < 4; nn++) {
            int row = m0 + mt*16 + trow;
            int col = qo + nn*8 + tcol;
            size_t i0 = (size_t)(t0 + row) * 192 + col;
            size_t i1 = (size_t)(t0 + row + 8) * 192 + col;
            split_store(g_ath, g_atl, i0,     oacc[mt][nn][0] * rs[mt][0]);
            split_store(g_ath, g_atl, i0 + 1, oacc[mt][nn][1] * rs[mt][0]);
            split_store(g_ath, g_atl, i1,     oacc[mt][nn][2] * rs[mt][1]);
            split_store(g_ath, g_atl, i1 + 1, oacc[mt][nn][3] * rs[mt][1]);
        }
    }
}

// =====================================================================
// k_ln2: LN(xh2) -> xn hi/lo planes
// =====================================================================
__global__ __launch_bounds__(256) void k_ln2(
    const float* __restrict__ w2, const float* __restrict__ b2)
{
    int t = blockIdx.x * 8 + (threadIdx.x >> 5);
    int lane = threadIdx.x & 31;
    const float* rp = g_xh2 + (size_t)t * DIMC;
    float v[6];
    float s = 0.f, sq = 0.f;
    #pragma unroll
    for (int k = 0; k < 6; k++) {
        v[k] = rp[lane + k*32];
        s += v[k]; sq += v[k]*v[k];
    }
    #pragma unroll
    for (int off = 16; off > 0; off >>= 1) {
        s  += __shfl_xor_sync(0xffffffffu, s,  off);
        sq += __shfl_xor_sync(0xffffffffu, sq, off);
    }
    float m = s * (1.0f/DIMC);
    float var = sq * (1.0f/DIMC) - m*m;
    float rstd = rsqrtf(var + 1e-5f);
    #pragma unroll
    for (int k = 0; k < 6; k++) {
        int c = lane + k*32;
        float o = (v[k] - m) * rstd * w2[c] + b2[c];
        split_store(g_xnh, g_xnl, (size_t)t * DIMC + c, o);
    }
}

// =====================================================================
// k_post: final (g_xres, fp32 [T,192]) -> NCHW out
// =====================================================================
__global__ __launch_bounds__(256) void k_post(float* __restrict__ out)
{
    __shared__ float os[DIMC][33];
    int w0 = blockIdx.x * 32, h = blockIdx.y, b = blockIdx.z;
    int tid = threadIdx.x, lane = tid & 31, wrp = tid >> 5;
    int whh = h >> 3, r = h & 7;

    #pragma unroll
    for (int it = 0; it < 24; it++) {
        int flat = it * 256 + tid;
        int tokj = flat / 192, c = flat - tokj * 192;
        int w = w0 + tokj, ww = w >> 3, cp = w & 7;
        int trow = ((b*32 + whh)*32 + ww)*64 + r*8 + cp;
        os[c][tokj] = g_xres[(size_t)trow*DIMC + c];
    }
    __syncthreads();
    #pragma unroll
    for (int it = 0; it < 24; it++) {
        int c = it * 8 + wrp;
        out[((size_t)(b*DIMC + c)*Hh + h)*Wc + w0 + lane] = os[c][lane];
    }
}

// =====================================================================
extern "C" void kernel_launch(void* const* d_in, const int* in_sizes, int n_in,
                              void* d_out, int out_size)
{
    const float* x     = (const float*)d_in[0];
    const float* bpe   = (const float*)d_in[1];
    const float* ln1w  = (const float*)d_in[2];
    const float* ln1b  = (const float*)d_in[3];
    const float* qkvw  = (const float*)d_in[4];
    const float* qkvb  = (const float*)d_in[5];
    const float* bpew  = (const float*)d_in[6];
    const float* bpeb  = (const float*)d_in[7];
    const float* projw = (const float*)d_in[8];
    const float* projb = (const float*)d_in[9];
    const float* ln2w  = (const float*)d_in[10];
    const float* ln2b  = (const float*)d_in[11];
    const float* fc1w  = (const float*)d_in[12];
    const float* fc1b  = (const float*)d_in[13];
    const float* fc2w  = (const float*)d_in[14];
    const float* fc2b  = (const float*)d_in[15];
    float* out = (float*)d_out;

    bf16 *wqh,*wql,*wbh,*wbl,*wph,*wpl,*w1h,*w1l,*w2h,*w2l;
    bf16 *xnh,*xnl,*bwh,*bwl,*ath,*atl,*h1h,*h1l;
    float *xres,*qkvf,*bqkf,*xh2;
    cudaGetSymbolAddress((void**)&wqh, g_wqh); cudaGetSymbolAddress((void**)&wql, g_wql);
    cudaGetSymbolAddress((void**)&wbh, g_wbh); cudaGetSymbolAddress((void**)&wbl, g_wbl);
    cudaGetSymbolAddress((void**)&wph, g_wph); cudaGetSymbolAddress((void**)&wpl, g_wpl);
    cudaGetSymbolAddress((void**)&w1h, g_w1h); cudaGetSymbolAddress((void**)&w1l, g_w1l);
    cudaGetSymbolAddress((void**)&w2h, g_w2h); cudaGetSymbolAddress((void**)&w2l, g_w2l);
    cudaGetSymbolAddress((void**)&xnh, g_xnh); cudaGetSymbolAddress((void**)&xnl, g_xnl);
    cudaGetSymbolAddress((void**)&bwh, g_bwh); cudaGetSymbolAddress((void**)&bwl, g_bwl);
    cudaGetSymbolAddress((void**)&ath, g_ath); cudaGetSymbolAddress((void**)&atl, g_atl);
    cudaGetSymbolAddress((void**)&h1h, g_h1h); cudaGetSymbolAddress((void**)&h1l, g_h1l);
    cudaGetSymbolAddress((void**)&xres, g_xres);
    cudaGetSymbolAddress((void**)&qkvf, g_qkv);
    cudaGetSymbolAddress((void**)&bqkf, g_bqk);
    cudaGetSymbolAddress((void**)&xh2,  g_xh2);

    // bf16 hi/lo planes aliased into the fp32 buffers (exact byte fit)
    bf16* qkvh = (bf16*)qkvf;
    bf16* qkvl = qkvh + (size_t)TTOT*576;
    bf16* bqkh = (bf16*)bqkf;
    bf16* bqkl = bqkh + (size_t)TTOT*384;

    dim3 wtb(32, 8);
    k_wt<<<dim3(576/32, 192/32), wtb>>>(qkvw, wqh, wql, 192, 576);
    k_wt<<<dim3(384/32,  32/32), wtb>>>(bpew, wbh, wbl,  32, 384);
    k_wt<<<dim3(192/32, 192/32), wtb>>>(projw, wph, wpl, 192, 192);
    k_wt<<<dim3(768/32, 192/32), wtb>>>(fc1w, w1h, w1l, 192, 768);
    k_wt<<<dim3(192/32, 768/32), wtb>>>(fc2w, w2h, w2l, 768, 192);

    // 1. transpose + LN1 (-> hi/lo) + bpe (-> hi/lo)
    k_pre<<<dim3(Wc/32, Hh, Bb), 256>>>(x, bpe, ln1w, ln1b);
    // 2. qkv = xn @ qkv_w + b  -> bf16 hi/lo [T,576]
    k_hmma<3><<<dim3(576/96, TTOT/128), 256, SMEM_HM>>>(xnh, xnl, wqh, wql, qkvb, nullptr, nullptr, qkvh, qkvl, 576, 192);
    // 3. bqk = bw @ bpe_w + b  -> bf16 hi/lo [T,384]
    k_hmma<3><<<dim3(384/96, TTOT/128), 256, SMEM_HM>>>(bwh, bwl, wbh, wbl, bpeb, nullptr, nullptr, bqkh, bqkl, 384, 32);
    // 4. attention (HMMA) -> attn hi/lo
    k_attn2<<<dim3(NHEAD, NWIN), 64>>>(qkvh, qkvl, bqkh, bqkl);
    // 5. xh2 = attn @ proj_w + b + shortcut  -> fp32 [T,192]
    k_hmma<1><<<dim3(192/96, TTOT/128), 256, SMEM_HM>>>(ath, atl, wph, wpl, projb, xres, xh2, nullptr, nullptr, 192, 192);
    // 6. LN2 -> xn hi/lo
    k_ln2<<<TTOT/8, 256>>>(ln2w, ln2b);
    // 7. h1 = gelu(xn @ fc1_w + b)  -> bf16 hi/lo [T,768]
    k_hmma<2><<<dim3(768/96, TTOT/128), 256, SMEM_HM>>>(xnh, xnl, w1h, w1l, fc1b, nullptr, nullptr, h1h, h1l, 768, 192);
    // 8. final = h1 @ fc2_w + b + xh2  -> fp32 (into dead g_xres)
    k_hmma<1><<<dim3(192/96, TTOT/128), 256, SMEM_HM>>>(h1h, h1l, w2h, w2l, fc2b, xh2, xres, nullptr, nullptr, 192, 768);
    // 9. window layout -> NCHW
    k_post<<<dim3(Wc/32, Hh, Bb), 256>>>(out);
}

// round 7
// speedup vs baseline: 1.0036x; 1.0036x over previous
#include <cuda_runtime.h>
#include <cuda_bf16.h>
#include <math.h>
#include <stdint.h>

#define Bb    4
#define DIMC  192
#define Hh    256
#define Wc    256
#define NHEAD 6
#define KBPE  32
#define NWIN  4096
#define TTOT  (Bb*Hh*Wc)   // 262144 tokens

typedef unsigned long long ull;
typedef __nv_bfloat16 bf16;

// ---------------- scratch ----------------
__device__ __align__(16) float g_xres[(size_t)TTOT*DIMC];   // shortcut; later fc2 fp32 out
__device__ __align__(16) bf16  g_xnh [(size_t)TTOT*DIMC];
__device__ __align__(16) bf16  g_xnl [(size_t)TTOT*DIMC];
__device__ __align__(16) bf16  g_bwh [(size_t)TTOT*KBPE];
__device__ __align__(16) bf16  g_bwl [(size_t)TTOT*KBPE];
__device__ __align__(16) float g_qkv [(size_t)TTOT*3*DIMC]; // aliased: bf16 hi|lo planes
__device__ __align__(16) float g_bqk [(size_t)TTOT*2*DIMC]; // aliased: bf16 hi|lo planes
__device__ __align__(16) bf16  g_ath [(size_t)TTOT*DIMC];
__device__ __align__(16) bf16  g_atl [(size_t)TTOT*DIMC];
__device__ __align__(16) float g_xh2 [(size_t)TTOT*DIMC];
__device__ __align__(16) bf16  g_h1h [(size_t)TTOT*4*DIMC];
__device__ __align__(16) bf16  g_h1l [(size_t)TTOT*4*DIMC];
// weights transposed [N,K], split hi/lo
__device__ __align__(16) bf16 g_wqh[576*192], g_wql[576*192];
__device__ __align__(16) bf16 g_wbh[384*32],  g_wbl[384*32];
__device__ __align__(16) bf16 g_wph[192*192], g_wpl[192*192];
__device__ __align__(16) bf16 g_w1h[768*192], g_w1l[768*192];
__device__ __align__(16) bf16 g_w2h[192*768], g_w2l[192*768];

// ---------------- helpers ----------------
__device__ __forceinline__ float gelu_exact(float x) {
    return 0.5f * x * (1.0f + erff(x * 0.70710678118654752440f));
}
__device__ __forceinline__ uint32_t smem_u32(const void* p) {
    uint32_t a;
    asm("{ .reg .u64 t; cvta.to.shared.u64 t, %1; cvt.u32.u64 %0, t; }" : "=r"(a) : "l"(p));
    return a;
}
__device__ __forceinline__ void split_store(bf16* hi, bf16* lo, size_t idx, float v) {
    bf16 h = __float2bfloat16(v);
    hi[idx] = h;
    lo[idx] = __float2bfloat16(v - __bfloat162float(h));
}
__device__ __forceinline__ float ex2f(float x) {
    float r; asm("ex2.approx.f32 %0, %1;" : "=f"(r) : "f"(x)); return r;
}
// pack two f32 -> bf16x2 (lo = a, hi = b)
__device__ __forceinline__ uint32_t packbf(float a, float b) {
    uint32_t r; asm("cvt.rn.bf16x2.f32 %0, %1, %2;" : "=r"(r) : "f"(b), "f"(a)); return r;
}
__device__ __forceinline__ float bfround(float x) {
    return __bfloat162float(__float2bfloat16(x));
}

// cp.async
__device__ __forceinline__ void cpa16(uint32_t dst, const void* src) {
    asm volatile("cp.async.ca.shared.global [%0], [%1], 16;" :: "r"(dst), "l"(src));
}
#define CP_COMMIT() asm volatile("cp.async.commit_group;" ::: "memory")
#define CP_WAIT1()  asm volatile("cp.async.wait_group 1;" ::: "memory")
#define CP_WAIT0()  asm volatile("cp.async.wait_group 0;" ::: "memory")

// ldmatrix (non-trans) x4
__device__ __forceinline__ void ldsm_x4(uint32_t* r, uint32_t addr) {
    asm volatile("ldmatrix.sync.aligned.m8n8.x4.shared.b16 {%0,%1,%2,%3}, [%4];"
        : "=r"(r[0]), "=r"(r[1]), "=r"(r[2]), "=r"(r[3]) : "r"(addr));
}
// bf16 mma m16n8k16, fp32 acc
__device__ __forceinline__ void mma_bf16(float* d, const uint32_t* a, const uint32_t* b) {
    asm volatile("mma.sync.aligned.m16n8k16.row.col.f32.bf16.bf16.f32 "
        "{%0,%1,%2,%3}, {%4,%5,%6,%7}, {%8,%9}, {%0,%1,%2,%3};"
        : "+f"(d[0]), "+f"(d[1]), "+f"(d[2]), "+f"(d[3])
        : "r"(a[0]), "r"(a[1]), "r"(a[2]), "r"(a[3]), "r"(b[0]), "r"(b[1]));
}

// =====================================================================
// k_wt: weight [K,N] fp32 -> [N,K] bf16 hi/lo
// =====================================================================
__global__ __launch_bounds__(256) void k_wt(const float* __restrict__ w,
                                            bf16* __restrict__ hi, bf16* __restrict__ lo,
                                            int K, int N)
{
    __shared__ float sm[32][33];
    int n0 = blockIdx.x * 32, k0 = blockIdx.y * 32;
    int tx = threadIdx.x, ty = threadIdx.y;
    #pragma unroll
    for (int j = 0; j < 32; j += 8)
        sm[ty + j][tx] = w[(size_t)(k0 + ty + j) * N + n0 + tx];
    __syncthreads();
    #pragma unroll
    for (int j = 0; j < 32; j += 8) {
        int n = n0 + ty + j, k = k0 + tx;
        split_store(hi, lo, (size_t)n * K + k, sm[tx][ty + j]);
    }
}

// =====================================================================
// k_pre: NCHW -> window layout, LN1 -> hi/lo planes, bpe -> hi/lo
// =====================================================================
__global__ __launch_bounds__(256) void k_pre(
    const float* __restrict__ x, const float* __restrict__ bpe,
    const float* __restrict__ w1, const float* __restrict__ b1)
{
    __shared__ float xs[DIMC][33];
    __shared__ float bs[KBPE][33];
    __shared__ float smean[32], srstd[32];
    int w0 = blockIdx.x * 32, h = blockIdx.y, b = blockIdx.z;
    int tid = threadIdx.x, lane = tid & 31, wrp = tid >> 5;

    #pragma unroll
    for (int it = 0; it < 24; it++) {
        int c = it * 8 + wrp;
        xs[c][lane] = x[((size_t)(b*DIMC + c)*Hh + h)*Wc + w0 + lane];
    }
    #pragma unroll
    for (int it = 0; it < 4; it++) {
        int c = it * 8 + wrp;
        bs[c][lane] = bpe[((size_t)(b*KBPE + c)*Hh + h)*Wc + w0 + lane];
    }
    __syncthreads();

    int tok = tid >> 3, g = tid & 7;
    float s = 0.f, sq = 0.f;
    for (int c = g; c < DIMC; c += 8) { float v = xs[c][tok]; s += v; sq += v*v; }
    s  += __shfl_down_sync(0xffffffffu, s, 4, 8);  sq += __shfl_down_sync(0xffffffffu, sq, 4, 8);
    s  += __shfl_down_sync(0xffffffffu, s, 2, 8);  sq += __shfl_down_sync(0xffffffffu, sq, 2, 8);
    s  += __shfl_down_sync(0xffffffffu, s, 1, 8);  sq += __shfl_down_sync(0xffffffffu, sq, 1, 8);
    if (g == 0) {
        float m = s * (1.0f/DIMC);
        float var = sq * (1.0f/DIMC) - m*m;
        smean[tok] = m;
        srstd[tok] = rsqrtf(var + 1e-5f);
    }
    __syncthreads();

    int whh = h >> 3, r = h & 7;
    #pragma unroll
    for (int it = 0; it < 24; it++) {
        int flat = it * 256 + tid;
        int tokj = flat / 192, c = flat - tokj * 192;
        int w = w0 + tokj, ww = w >> 3, cp = w & 7;
        int trow = ((b*32 + whh)*32 + ww)*64 + r*8 + cp;
        float v = xs[c][tokj];
        g_xres[(size_t)trow*DIMC + c] = v;
        float vn = (v - smean[tokj]) * srstd[tokj] * w1[c] + b1[c];
        split_store(g_xnh, g_xnl, (size_t)trow*DIMC + c, vn);
    }
    #pragma unroll
    for (int it = 0; it < 4; it++) {
        int flat = it * 256 + tid;
        int tokj = flat >> 5, c = flat & 31;
        int w = w0 + tokj, ww = w >> 3, cp = w & 7;
        int trow = ((b*32 + whh)*32 + ww)*64 + r*8 + cp;
        split_store(g_bwh, g_bwl, (size_t)trow*KBPE + c, bs[c][tokj]);
    }
}

// =====================================================================
// k_hmma: C = A @ W^T via mma.sync bf16 3-pass split.
// CTA 128x96, KC=16, 8 warps (4x2), warp 32x48 = 2x6 m16n8k16 tiles.
// MODE 0: +bias fp32 ; 1: +bias+res fp32 ; 2: gelu -> bf16 hi/lo ;
// MODE 3: +bias -> bf16 hi/lo (no activation)
// =====================================================================
#define STAGE_B 21504
#define SMEM_HM (2*STAGE_B)

template<int MODE>
__global__ __launch_bounds__(256, 2) void k_hmma(
    const bf16* __restrict__ Ahi, const bf16* __restrict__ Alo,
    const bf16* __restrict__ Bhi, const bf16* __restrict__ Blo,
    const float* __restrict__ bias, const float* __restrict__ res,
    float* __restrict__ Cf, bf16* __restrict__ Chi, bf16* __restrict__ Clo,
    int N, int K)
{
    extern __shared__ char smc[];
    const uint32_t sb = smem_u32(smc);
    const int tid = threadIdx.x, lane = tid & 31, wid = tid >> 5;
    const int bx = blockIdx.x, by = blockIdx.y;
    const int mrow = (wid & 3) * 32, ncol = (wid >> 2) * 48;

    float acc[2][6][4];
    #pragma unroll
    for (int i = 0; i < 2; i++)
        #pragma unroll
        for (int j = 0; j < 6; j++)
            #pragma unroll
            for (int q = 0; q < 4; q++) acc[i][j][q] = 0.f;

    const int a_row_l = ((lane >> 3) & 1) * 8 + (lane & 7);
    const int a_k_l   = (lane >> 4) * 8;
    const int b_n_l   = (lane >> 4) * 8 + (lane & 7);
    const int b_k_l   = ((lane >> 3) & 1) * 8;

    const int nt = K / 16;

    auto load_stage = [&](int s, int k0) {
        uint32_t base = sb + s * STAGE_B;
        #pragma unroll
        for (int it = 0; it < 2; it++) {
            int id = it * 256 + tid;
            int pl = id >> 8, rem = id & 255;
            int row = rem >> 1, seg = rem & 1;
            const bf16* src = (pl ? Alo : Ahi) + (size_t)(by*128 + row) * K + k0 + seg*8;
            cpa16(base + pl*6144 + row*48 + seg*16, src);
        }
        {
            int id = tid;
            int pl = (id >= 192), rem = id - pl*192;
            int row = rem >> 1, seg = rem & 1;
            const bf16* src = (pl ? Blo : Bhi) + (size_t)(bx*96 + row) * K + k0 + seg*8;
            cpa16(base + 12288 + pl*4608 + row*48 + seg*16, src);
        }
        if (tid < 128) {
            int id = 256 + tid;
            int pl = (id >= 192), rem = id - pl*192;
            int row = rem >> 1, seg = rem & 1;
            const bf16* src = (pl ? Blo : Bhi) + (size_t)(bx*96 + row) * K + k0 + seg*8;
            cpa16(base + 12288 + pl*4608 + row*48 + seg*16, src);
        }
        CP_COMMIT();
    };

    load_stage(0, 0);

    for (int t = 0; t < nt; t++) {
        if (t + 1 < nt) { load_stage((t + 1) & 1, (t + 1) * 16); CP_WAIT1(); }
        else            { CP_WAIT0(); }
        __syncthreads();

        uint32_t base = sb + (t & 1) * STAGE_B;
        uint32_t Ah[2][4], Al_[2][4], Bf[6][2];
        #pragma unroll
        for (int mt = 0; mt < 2; mt++) {
            uint32_t off = (mrow + mt*16 + a_row_l) * 48 + a_k_l * 2;
            ldsm_x4(Ah[mt],  base + off);
            ldsm_x4(Al_[mt], base + 6144 + off);
        }
        #pragma unroll
        for (int nb = 0; nb < 3; nb++) {
            uint32_t r4[4];
            ldsm_x4(r4, base + 12288 + (ncol + nb*16 + b_n_l) * 48 + b_k_l * 2);
            Bf[nb*2][0] = r4[0]; Bf[nb*2][1] = r4[1];
            Bf[nb*2+1][0] = r4[2]; Bf[nb*2+1][1] = r4[3];
        }
        #pragma unroll
        for (int mt = 0; mt < 2; mt++)
            #pragma unroll
            for (int nn = 0; nn < 6; nn++) {
                mma_bf16(acc[mt][nn], Ah[mt],  Bf[nn]);
                mma_bf16(acc[mt][nn], Al_[mt], Bf[nn]);
            }
        #pragma unroll
        for (int nb = 0; nb < 3; nb++) {
            uint32_t r4[4];
            ldsm_x4(r4, base + 16896 + (ncol + nb*16 + b_n_l) * 48 + b_k_l * 2);
            Bf[nb*2][0] = r4[0]; Bf[nb*2][1] = r4[1];
            Bf[nb*2+1][0] = r4[2]; Bf[nb*2+1][1] = r4[3];
        }
        #pragma unroll
        for (int mt = 0; mt < 2; mt++)
            #pragma unroll
            for (int nn = 0; nn < 6; nn++)
                mma_bf16(acc[mt][nn], Ah[mt], Bf[nn]);
        __syncthreads();
    }

    // ---- epilogue ----
    const int trow = lane >> 2, tcol = (lane & 3) * 2;
    #pragma unroll
    for (int mt = 0; mt < 2; mt++) {
        #pragma unroll
        for (int nn = 0; nn < 6; nn++) {
            int row0 = by*128 + mrow + mt*16 + trow;
            int col  = bx*96 + ncol + nn*8 + tcol;
            float b0 = bias[col], b1 = bias[col + 1];
            #pragma unroll
            for (int hh = 0; hh < 2; hh++) {
                int row = row0 + hh * 8;
                float v0 = acc[mt][nn][hh*2]   + b0;
                float v1 = acc[mt][nn][hh*2+1] + b1;
                size_t idx = (size_t)row * N + col;
                if (MODE == 1) { v0 += res[idx]; v1 += res[idx + 1]; }
                if (MODE == 2) {
                    split_store(Chi, Clo, idx,     gelu_exact(v0));
                    split_store(Chi, Clo, idx + 1, gelu_exact(v1));
                } else if (MODE == 3) {
                    split_store(Chi, Clo, idx,     v0);
                    split_store(Chi, Clo, idx + 1, v1);
                } else {
                    *(float2*)(Cf + idx) = make_float2(v0, v1);
                }
            }
        }
    }
}

// =====================================================================
// k_attn2: HMMA attention. Block = (head, window), 2 warps, 64 threads.
// S = [Q|Bq][64,64] @ [K|Bk][64,64]^T (3-pass hi/lo), softmax in regs,
// P repacked in-register to A-frags, P@V (3-pass). 45KB static smem.
// =====================================================================
#define APITCH 144
#define QH_OFF 0
#define QL_OFF 9216
#define KH_OFF 18432
#define KL_OFF 27648
#define VH_OFF 36864
#define VL_OFF 41472

__global__ __launch_bounds__(64) void k_attn2(
    const bf16* __restrict__ qkvh, const bf16* __restrict__ qkvl,
    const bf16* __restrict__ bqkh, const bf16* __restrict__ bqkl)
{
    __shared__ __align__(16) char sm[46080];
    const uint32_t sb = smem_u32(sm);
    const int hd = blockIdx.x, win = blockIdx.y;
    const int tid = threadIdx.x, lane = tid & 31, wrp = tid >> 5;
    const int t0 = win * 64, qo = hd * 32;

    // ---- load Q|Bq, K|Bk rows (one row per thread), V transposed ----
    {
        int i = tid;
        const uint4* qh = (const uint4*)(qkvh + (size_t)(t0+i)*576 + qo);
        const uint4* ql = (const uint4*)(qkvl + (size_t)(t0+i)*576 + qo);
        const uint4* kh = (const uint4*)(qkvh + (size_t)(t0+i)*576 + 192 + qo);
        const uint4* kl = (const uint4*)(qkvl + (size_t)(t0+i)*576 + 192 + qo);
        const uint4* bh = (const uint4*)(bqkh + (size_t)(t0+i)*384 + qo);
        const uint4* bl = (const uint4*)(bqkl + (size_t)(t0+i)*384 + qo);
        const uint4* ch = (const uint4*)(bqkh + (size_t)(t0+i)*384 + 192 + qo);
        const uint4* cl = (const uint4*)(bqkl + (size_t)(t0+i)*384 + 192 + qo);
        uint4* dqh = (uint4*)(sm + QH_OFF + i*APITCH);
        uint4* dql = (uint4*)(sm + QL_OFF + i*APITCH);
        uint4* dkh = (uint4*)(sm + KH_OFF + i*APITCH);
        uint4* dkl = (uint4*)(sm + KL_OFF + i*APITCH);
        #pragma unroll
        for (int j = 0; j < 4; j++) {
            dqh[j] = qh[j]; dqh[4+j] = bh[j];
            dql[j] = ql[j]; dql[4+j] = bl[j];
            dkh[j] = kh[j]; dkh[4+j] = ch[j];
            dkl[j] = kl[j]; dkl[4+j] = cl[j];
        }
    }
    #pragma unroll
    for (int it = 0; it < 32; it++) {
        int t = it*2 + wrp;
        int d = lane;
        *(bf16*)(sm + VH_OFF + d*APITCH + t*2) = qkvh[(size_t)(t0+t)*576 + 384 + qo + d];
        *(bf16*)(sm + VL_OFF + d*APITCH + t*2) = qkvl[(size_t)(t0+t)*576 + 384 + qo + d];
    }
    __syncthreads();

    const int m0 = wrp * 32;
    const int a_row_l = ((lane >> 3) & 1) * 8 + (lane & 7);
    const int a_k_l   = (lane >> 4) * 8;
    const int b_n_l   = (lane >> 4) * 8 + (lane & 7);
    const int b_k_l   = ((lane >> 3) & 1) * 8;

    // ---- S = Qcat @ Kcat^T, 3-pass ----
    float sacc[2][8][4];
    #pragma unroll
    for (int i = 0; i < 2; i++)
        #pragma unroll
        for (int j = 0; j < 8; j++)
            #pragma unroll
            for (int q = 0; q < 4; q++) sacc[i][j][q] = 0.f;

    #pragma unroll
    for (int kt = 0; kt < 4; kt++) {
        uint32_t Ah[2][4], Al[2][4], Bh[8][2], Bl[8][2];
        #pragma unroll
        for (int mt = 0; mt < 2; mt++) {
            uint32_t off = (m0 + mt*16 + a_row_l) * APITCH + (kt*16 + a_k_l) * 2;
            ldsm_x4(Ah[mt], sb + QH_OFF + off);
            ldsm_x4(Al[mt], sb + QL_OFF + off);
        }
        #pragma unroll
        for (int nb = 0; nb < 4; nb++) {
            uint32_t r4[4];
            uint32_t off = (nb*16 + b_n_l) * APITCH + (kt*16 + b_k_l) * 2;
            ldsm_x4(r4, sb + KH_OFF + off);
            Bh[nb*2][0] = r4[0]; Bh[nb*2][1] = r4[1];
            Bh[nb*2+1][0] = r4[2]; Bh[nb*2+1][1] = r4[3];
            ldsm_x4(r4, sb + KL_OFF + off);
            Bl[nb*2][0] = r4[0]; Bl[nb*2][1] = r4[1];
            Bl[nb*2+1][0] = r4[2]; Bl[nb*2+1][1] = r4[3];
        }
        #pragma unroll
        for (int mt = 0; mt < 2; mt++)
            #pragma unroll
            for (int nn = 0; nn < 8; nn++) {
                mma_bf16(sacc[mt][nn], Ah[mt], Bh[nn]);
                mma_bf16(sacc[mt][nn], Ah[mt], Bl[nn]);
                mma_bf16(sacc[mt][nn], Al[mt], Bh[nn]);
            }
    }

    // ---- softmax over each row of 64 (quad shfl reduce) ----
    const float cs = 0.25503486325804f;   // (1/sqrt(32)) * log2(e)
    float rs[2][2];
    #pragma unroll
    for (int mt = 0; mt < 2; mt++) {
        float mA = -1e30f, mB = -1e30f;
        #pragma unroll
        for (int n = 0; n < 8; n++) {
            mA = fmaxf(mA, fmaxf(sacc[mt][n][0], sacc[mt][n][1]));
            mB = fmaxf(mB, fmaxf(sacc[mt][n][2], sacc[mt][n][3]));
        }
        mA = fmaxf(mA, __shfl_xor_sync(0xffffffffu, mA, 1));
        mA = fmaxf(mA, __shfl_xor_sync(0xffffffffu, mA, 2));
        mB = fmaxf(mB, __shfl_xor_sync(0xffffffffu, mB, 1));
        mB = fmaxf(mB, __shfl_xor_sync(0xffffffffu, mB, 2));
        float sA = 0.f, sB = 0.f;
        #pragma unroll
        for (int n = 0; n < 8; n++) {
            float p0 = ex2f((sacc[mt][n][0] - mA) * cs);
            float p1 = ex2f((sacc[mt][n][1] - mA) * cs);
            float p2 = ex2f((sacc[mt][n][2] - mB) * cs);
            float p3 = ex2f((sacc[mt][n][3] - mB) * cs);
            sacc[mt][n][0] = p0; sacc[mt][n][1] = p1;
            sacc[mt][n][2] = p2; sacc[mt][n][3] = p3;
            sA += p0 + p1; sB += p2 + p3;
        }
        sA += __shfl_xor_sync(0xffffffffu, sA, 1);
        sA += __shfl_xor_sync(0xffffffffu, sA, 2);
        sB += __shfl_xor_sync(0xffffffffu, sB, 1);
        sB += __shfl_xor_sync(0xffffffffu, sB, 2);
        rs[mt][0] = 1.0f / sA;
        rs[mt][1] = 1.0f / sB;
    }

    // ---- out = P @ V, 3-pass (P hi/lo in-register repack) ----
    float oacc[2][4][4];
    #pragma unroll
    for (int i = 0; i < 2; i++)
        #pragma unroll
        for (int j = 0; j < 4; j++)
            #pragma unroll
            for (int q = 0; q < 4; q++) oacc[i][j][q] = 0.f;

    #pragma unroll
    for (int kt = 0; kt < 4; kt++) {
        uint32_t Ph[2][4], Pl[2][4];
        #pragma unroll
        for (int mt = 0; mt < 2; mt++) {
            float p00 = sacc[mt][2*kt][0],   p01 = sacc[mt][2*kt][1];
            float p02 = sacc[mt][2*kt][2],   p03 = sacc[mt][2*kt][3];
            float p10 = sacc[mt][2*kt+1][0], p11 = sacc[mt][2*kt+1][1];
            float p12 = sacc[mt][2*kt+1][2], p13 = sacc[mt][2*kt+1][3];
            Ph[mt][0] = packbf(p00, p01);
            Ph[mt][1] = packbf(p02, p03);
            Ph[mt][2] = packbf(p10, p11);
            Ph[mt][3] = packbf(p12, p13);
            Pl[mt][0] = packbf(p00 - bfround(p00), p01 - bfround(p01));
            Pl[mt][1] = packbf(p02 - bfround(p02), p03 - bfround(p03));
            Pl[mt][2] = packbf(p10 - bfround(p10), p11 - bfround(p11));
            Pl[mt][3] = packbf(p12 - bfround(p12), p13 - bfround(p13));
        }
        uint32_t Vh[4][2], Vl[4][2];
        #pragma unroll
        for (int nb = 0; nb < 2; nb++) {
            uint32_t r4[4];
            uint32_t off = (nb*16 + b_n_l) * APITCH + (kt*16 + b_k_l) * 2;
            ldsm_x4(r4, sb + VH_OFF + off);
            Vh[nb*2][0] = r4[0]; Vh[nb*2][1] = r4[1];
            Vh[nb*2+1][0] = r4[2]; Vh[nb*2+1][1] = r4[3];
            ldsm_x4(r4, sb + VL_OFF + off);
            Vl[nb*2][0] = r4[0]; Vl[nb*2][1] = r4[1];
            Vl[nb*2+1][0] = r4[2]; Vl[nb*2+1][1] = r4[3];
        }
        #pragma unroll
        for (int mt = 0; mt < 2; mt++)
            #pragma unroll
            for (int nn = 0; nn < 4; nn++) {
                mma_bf16(oacc[mt][nn], Ph[mt], Vh[nn]);
                mma_bf16(oacc[mt][nn], Ph[mt], Vl[nn]);
                mma_bf16(oacc[mt][nn], Pl[mt], Vh[nn]);
            }
    }

    // ---- epilogue: scale by 1/rowsum, split-store bf16 hi/lo ----
    const int trow = lane >> 2, tcol = (lane & 3) * 2;
    #pragma unroll
    for (int mt = 0; mt < 2; mt++) {
        #pragma unroll
        for (int nn = 0; nn < 4; nn++) {
            int row = m0 + mt*16 + trow;
            int col = qo + nn*8 + tcol;
            size_t i0 = (size_t)(t0 + row) * 192 + col;
            size_t i1 = (size_t)(t0 + row + 8) * 192 + col;
            split_store(g_ath, g_atl, i0,     oacc[mt][nn][0] * rs[mt][0]);
            split_store(g_ath, g_atl, i0 + 1, oacc[mt][nn][1] * rs[mt][0]);
            split_store(g_ath, g_atl, i1,     oacc[mt][nn][2] * rs[mt][1]);
            split_store(g_ath, g_atl, i1 + 1, oacc[mt][nn][3] * rs[mt][1]);
        }
    }
}

// =====================================================================
// k_ln2: LN(xh2) -> xn hi/lo planes
// =====================================================================
__global__ __launch_bounds__(256) void k_ln2(
    const float* __restrict__ w2, const float* __restrict__ b2)
{
    int t = blockIdx.x * 8 + (threadIdx.x >> 5);
    int lane = threadIdx.x & 31;
    const float* rp = g_xh2 + (size_t)t * DIMC;
    float v[6];
    float s = 0.f, sq = 0.f;
    #pragma unroll
    for (int k = 0; k < 6; k++) {
        v[k] = rp[lane + k*32];
        s += v[k]; sq += v[k]*v[k];
    }
    #pragma unroll
    for (int off = 16; off > 0; off >>= 1) {
        s  += __shfl_xor_sync(0xffffffffu, s,  off);
        sq += __shfl_xor_sync(0xffffffffu, sq, off);
    }
    float m = s * (1.0f/DIMC);
    float var = sq * (1.0f/DIMC) - m*m;
    float rstd = rsqrtf(var + 1e-5f);
    #pragma unroll
    for (int k = 0; k < 6; k++) {
        int c = lane + k*32;
        float o = (v[k] - m) * rstd * w2[c] + b2[c];
        split_store(g_xnh, g_xnl, (size_t)t * DIMC + c, o);
    }
}

// =====================================================================
// k_post: final (g_xres, fp32 [T,192]) -> NCHW out
// =====================================================================
__global__ __launch_bounds__(256) void k_post(float* __restrict__ out)
{
    __shared__ float os[DIMC][33];
    int w0 = blockIdx.x * 32, h = blockIdx.y, b = blockIdx.z;
    int tid = threadIdx.x, lane = tid & 31, wrp = tid >> 5;
    int whh = h >> 3, r = h & 7;

    #pragma unroll
    for (int it = 0; it < 24; it++) {
        int flat = it * 256 + tid;
        int tokj = flat / 192, c = flat - tokj * 192;
        int w = w0 + tokj, ww = w >> 3, cp = w & 7;
        int trow = ((b*32 + whh)*32 + ww)*64 + r*8 + cp;
        os[c][tokj] = g_xres[(size_t)trow*DIMC + c];
    }
    __syncthreads();
    #pragma unroll
    for (int it = 0; it < 24; it++) {
        int c = it * 8 + wrp;
        out[((size_t)(b*DIMC + c)*Hh + h)*Wc + w0 + lane] = os[c][lane];
    }
}

// =====================================================================
extern "C" void kernel_launch(void* const* d_in, const int* in_sizes, int n_in,
                              void* d_out, int out_size)
{
    const float* x     = (const float*)d_in[0];
    const float* bpe   = (const float*)d_in[1];
    const float* ln1w  = (const float*)d_in[2];
    const float* ln1b  = (const float*)d_in[3];
    const float* qkvw  = (const float*)d_in[4];
    const float* qkvb  = (const float*)d_in[5];
    const float* bpew  = (const float*)d_in[6];
    const float* bpeb  = (const float*)d_in[7];
    const float* projw = (const float*)d_in[8];
    const float* projb = (const float*)d_in[9];
    const float* ln2w  = (const float*)d_in[10];
    const float* ln2b  = (const float*)d_in[11];
    const float* fc1w  = (const float*)d_in[12];
    const float* fc1b  = (const float*)d_in[13];
    const float* fc2w  = (const float*)d_in[14];
    const float* fc2b  = (const float*)d_in[15];
    float* out = (float*)d_out;

    bf16 *wqh,*wql,*wbh,*wbl,*wph,*wpl,*w1h,*w1l,*w2h,*w2l;
    bf16 *xnh,*xnl,*bwh,*bwl,*ath,*atl,*h1h,*h1l;
    float *xres,*qkvf,*bqkf,*xh2;
    cudaGetSymbolAddress((void**)&wqh, g_wqh); cudaGetSymbolAddress((void**)&wql, g_wql);
    cudaGetSymbolAddress((void**)&wbh, g_wbh); cudaGetSymbolAddress((void**)&wbl, g_wbl);
    cudaGetSymbolAddress((void**)&wph, g_wph); cudaGetSymbolAddress((void**)&wpl, g_wpl);
    cudaGetSymbolAddress((void**)&w1h, g_w1h); cudaGetSymbolAddress((void**)&w1l, g_w1l);
    cudaGetSymbolAddress((void**)&w2h, g_w2h); cudaGetSymbolAddress((void**)&w2l, g_w2l);
    cudaGetSymbolAddress((void**)&xnh, g_xnh); cudaGetSymbolAddress((void**)&xnl, g_xnl);
    cudaGetSymbolAddress((void**)&bwh, g_bwh); cudaGetSymbolAddress((void**)&bwl, g_bwl);
    cudaGetSymbolAddress((void**)&ath, g_ath); cudaGetSymbolAddress((void**)&atl, g_atl);
    cudaGetSymbolAddress((void**)&h1h, g_h1h); cudaGetSymbolAddress((void**)&h1l, g_h1l);
    cudaGetSymbolAddress((void**)&xres, g_xres);
    cudaGetSymbolAddress((void**)&qkvf, g_qkv);
    cudaGetSymbolAddress((void**)&bqkf, g_bqk);
    cudaGetSymbolAddress((void**)&xh2,  g_xh2);

    // bf16 hi/lo planes aliased into the fp32 buffers (exact byte fit)
    bf16* qkvh = (bf16*)qkvf;
    bf16* qkvl = qkvh + (size_t)TTOT*576;
    bf16* bqkh = (bf16*)bqkf;
    bf16* bqkl = bqkh + (size_t)TTOT*384;

    dim3 wtb(32, 8);
    k_wt<<<dim3(576/32, 192/32), wtb>>>(qkvw, wqh, wql, 192, 576);
    k_wt<<<dim3(384/32,  32/32), wtb>>>(bpew, wbh, wbl,  32, 384);
    k_wt<<<dim3(192/32, 192/32), wtb>>>(projw, wph, wpl, 192, 192);
    k_wt<<<dim3(768/32, 192/32), wtb>>>(fc1w, w1h, w1l, 192, 768);
    k_wt<<<dim3(192/32, 768/32), wtb>>>(fc2w, w2h, w2l, 768, 192);

    // 1. transpose + LN1 (-> hi/lo) + bpe (-> hi/lo)
    k_pre<<<dim3(Wc/32, Hh, Bb), 256>>>(x, bpe, ln1w, ln1b);
    // 2. qkv = xn @ qkv_w + b  -> bf16 hi/lo [T,576]
    k_hmma<3><<<dim3(576/96, TTOT/128), 256, SMEM_HM>>>(xnh, xnl, wqh, wql, qkvb, nullptr, nullptr, qkvh, qkvl, 576, 192);
    // 3. bqk = bw @ bpe_w + b  -> bf16 hi/lo [T,384]
    k_hmma<3><<<dim3(384/96, TTOT/128), 256, SMEM_HM>>>(bwh, bwl, wbh, wbl, bpeb, nullptr, nullptr, bqkh, bqkl, 384, 32);
    // 4. attention (HMMA) -> attn hi/lo
    k_attn2<<<dim3(NHEAD, NWIN), 64>>>(qkvh, qkvl, bqkh, bqkl);
    // 5. xh2 = attn @ proj_w + b + shortcut  -> fp32 [T,192]
    k_hmma<1><<<dim3(192/96, TTOT/128), 256, SMEM_HM>>>(ath, atl, wph, wpl, projb, xres, xh2, nullptr, nullptr, 192, 192);
    // 6. LN2 -> xn hi/lo
    k_ln2<<<TTOT/8, 256>>>(ln2w, ln2b);
    // 7. h1 = gelu(xn @ fc1_w + b)  -> bf16 hi/lo [T,768]
    k_hmma<2><<<dim3(768/96, TTOT/128), 256, SMEM_HM>>>(xnh, xnl, w1h, w1l, fc1b, nullptr, nullptr, h1h, h1l, 768, 192);
    // 8. final = h1 @ fc2_w + b + xh2  -> fp32 (into dead g_xres)
    k_hmma<1><<<dim3(192/96, TTOT/128), 256, SMEM_HM>>>(h1h, h1l, w2h, w2l, fc2b, xh2, xres, nullptr, nullptr, 192, 768);
    // 9. window layout -> NCHW
    k_post<<<dim3(Wc/32, Hh, Bb), 256>>>(out);
}